// round 12
// baseline (speedup 1.0000x reference)
#include <cuda_runtime.h>
#include <cuda_fp16.h>
#include <stdint.h>

// ---------------------------------------------------------------------------
// TT-linear fused kernel, v12: 2 batch rows per CTA (512 thr, 1 CTA/SM),
// software-pipelined so every barrier region mixes tensor-heavy work of one
// row with memory-heavy work of the other. 5 syncs / 2 rows (was 10).
// stmatrix.x4.trans epilogue. f16 accumulators throughout (stage C too).
// ---------------------------------------------------------------------------

#define B_BUF0 0
#define B_BUF1 65536
#define B_YH0  131072
#define B_YH1  (131072 + 8704)
#define SMEM_BYTES (131072 + 2 * 8704 + 1024)

// fragment-ordered core matrices (fp16), layouts as v10/v11 (passing):
__device__ __half g_M1f[8 * 8 * 32 * 8];   // 32KB
__device__ __half g_M2f[16 * 32 * 4];      // 4KB
__device__ __half g_M0f[8 * 32 * 8];       // 4KB

__global__ void tt_prep_cores(const float* __restrict__ c0,
                              const float* __restrict__ c1,
                              const float* __restrict__ c2) {
    int t = blockIdx.x * blockDim.x + threadIdx.x;
    int lane = t & 31, g = (lane >> 2), c = lane & 3;
    if (t < 2048) {                       // M1f: (kk, nt, lane)
        int kk = t >> 8, nt = (t >> 5) & 7;
        #pragma unroll
        for (int r = 0; r < 4; r++)
            #pragma unroll
            for (int h = 0; h < 2; h++) {
                int n = 16 * nt + g + 8 * (r & 1);
                int k = 16 * kk + 8 * (r >> 1) + 2 * c + h;
                int o1 = n >> 3, r1 = n & 7, i1 = k >> 3, r2 = k & 7;
                g_M1f[t * 8 + r * 2 + h] =
                    __float2half(c1[((r1 * 16 + o1) * 16 + i1) * 8 + r2]);
            }
    }
    if (t < 512) {                        // M2f: (nt8, lane)
        int nt8 = t >> 5;
        #pragma unroll
        for (int r = 0; r < 2; r++)
            #pragma unroll
            for (int h = 0; h < 2; h++) {
                int n = 8 * nt8 + g;
                int k = 8 * r + 2 * c + h;            // logical mma-k
                int o2 = n >> 3, r2 = n & 7;
                int cc = (k >> 1) & 3, d = k & 1, e = k >> 3;
                int i2 = 4 * cc + 2 * e + d;          // sigma(k)
                g_M2f[t * 4 + r * 2 + h] =
                    __float2half(c2[(r2 * 16 + o2) * 16 + i2]);
            }
    }
    if (t < 256) {                        // M0f: (ks=0..7, lane)
        int ks = t >> 5;
        #pragma unroll
        for (int r = 0; r < 4; r++)
            #pragma unroll
            for (int h = 0; h < 2; h++) {
                int n = g + 8 * (r & 1);              // o0
                int k = 16 * ks + 8 * (r >> 1) + 2 * c + h;
                int i0 = k >> 3, r1 = k & 7;
                g_M0f[t * 8 + r * 2 + h] =
                    __float2half(c0[(n * 16 + i0) * 8 + r1]);
            }
    }
}

__device__ __forceinline__ void mma16816h(uint32_t* d, const uint32_t* a,
                                          uint32_t b0, uint32_t b1) {
    asm volatile(
        "mma.sync.aligned.m16n8k16.row.col.f16.f16.f16.f16 "
        "{%0,%1}, {%2,%3,%4,%5}, {%6,%7}, {%0,%1};\n"
        : "+r"(d[0]), "+r"(d[1])
        : "r"(a[0]), "r"(a[1]), "r"(a[2]), "r"(a[3]), "r"(b0), "r"(b1));
}

__device__ __forceinline__ void ldsm4(uint32_t* r, uint32_t addr) {
    asm volatile(
        "ldmatrix.sync.aligned.m8n8.x4.shared.b16 {%0,%1,%2,%3}, [%4];\n"
        : "=r"(r[0]), "=r"(r[1]), "=r"(r[2]), "=r"(r[3]) : "r"(addr));
}

__device__ __forceinline__ void stsm2(uint32_t addr, uint32_t r0, uint32_t r1) {
    asm volatile(
        "stmatrix.sync.aligned.m8n8.x2.shared.b16 [%0], {%1,%2};\n"
        :: "r"(addr), "r"(r0), "r"(r1) : "memory");
}

__device__ __forceinline__ void stsm4(uint32_t addr, uint32_t r0, uint32_t r1,
                                      uint32_t r2, uint32_t r3) {
    asm volatile(
        "stmatrix.sync.aligned.m8n8.x4.shared.b16 [%0], {%1,%2,%3,%4};\n"
        :: "r"(addr), "r"(r0), "r"(r1), "r"(r2), "r"(r3) : "memory");
}

__device__ __forceinline__ void stsm4t(uint32_t addr, uint32_t r0, uint32_t r1,
                                       uint32_t r2, uint32_t r3) {
    asm volatile(
        "stmatrix.sync.aligned.m8n8.x4.trans.shared.b16 [%0], {%1,%2,%3,%4};\n"
        :: "r"(addr), "r"(r0), "r"(r1), "r"(r2), "r"(r3) : "memory");
}

__device__ __forceinline__ uint32_t packh2(float lo, float hi) {
    __half2 h = __floats2half2_rn(lo, hi);
    return *(uint32_t*)&h;
}

__global__ void __launch_bounds__(512, 1)
tt_linear_kernel(const float* __restrict__ x, const float* __restrict__ bias,
                 float* __restrict__ y) {
    extern __shared__ __half smem[];
    uint32_t sbase;
    asm("{ .reg .u64 t; cvta.to.shared.u64 t, %1; cvt.u32.u64 %0, t; }"
        : "=r"(sbase) : "l"(smem));
    const uint32_t abase = (sbase + 1023) & ~1023u;
    char* scp = (char*)smem + (abase - sbase);

    const int b2   = blockIdx.x;            // rows 2*b2, 2*b2+1
    const int tid  = threadIdx.x;
    const int w    = tid >> 5;               // 0..15
    const int lane = tid & 31;
    const int g = lane >> 2, c = lane & 3;
    const int lsel = lane & 15;
    const int hi   = lane >> 4;
    const int msel = lane >> 3;               // 0..3
    const int mrow = lane & 7;

    const int mw = w & 7;                     // stage B m-warp (8)
    const int nw = w >> 3;                    // stage B n-warp (2)

    const float* xr0 = x + (size_t)(2 * b2) * 4096;
    const float* xr1 = xr0 + 4096;
    const uint4* M1v = (const uint4*)g_M1f;
    const uint2* M2v = (const uint2*)g_M2f;
    const uint4* M0v = (const uint4*)g_M0f;

    // ---- stage helpers ----
    auto loadpack = [&](const float* xr, uint32_t* a) {
        const float* rp = xr + w * 256 + 16 * g + 4 * c;   // i0 = w
        float4 f0 = *(const float4*)(rp);
        float4 f1 = *(const float4*)(rp + 128);
        a[0] = packh2(f0.x, f0.y);
        a[1] = packh2(f1.x, f1.y);
        a[2] = packh2(f0.z, f0.w);
        a[3] = packh2(f1.z, f1.w);
    };

    // A: x row (i0=w) @ M2^T -> T2 in buf (row = 16*i0+o2, chunk=i1, XOR ^(row&7))
    auto stageA = [&](const uint32_t* a, uint32_t bufo) {
        const int i1s = 8 * (msel & 1) + mrow;     // stsm.x2 source row
        #pragma unroll
        for (int nt8 = 0; nt8 < 16; nt8++) {
            uint2 bf = M2v[nt8 * 32 + lane];
            uint32_t d[2] = {0u, 0u};
            mma16816h(d, a, bf.x, bf.y);
            const uint32_t addr = abase + bufo +
                (uint32_t)(16 * w + nt8) * 256 +
                ((uint32_t)(i1s ^ (nt8 & 7)) << 4);
            stsm2(addr, d[0], d[1]);
        }
    };

    // B: T2 (256x128) @ M1^T; warp grid 8M x 2N, mi=2, jj=4; f16 acc 32 regs
    auto stageB = [&](uint32_t bufo, uint32_t (&acc)[2][8][2]) {
        #pragma unroll
        for (int mi = 0; mi < 2; mi++)
            #pragma unroll
            for (int s = 0; s < 8; s++) {
                acc[mi][s][0] = 0u; acc[mi][s][1] = 0u;
            }
        uint32_t abm[2];
        #pragma unroll
        for (int mi = 0; mi < 2; mi++) {
            const int ar = 32 * mw + 16 * mi + lsel;
            abm[mi] = abase + bufo + (uint32_t)ar * 256 +
                      ((uint32_t)(hi ^ (ar & 7)) << 4);
        }
        #pragma unroll
        for (int kk = 0; kk < 8; kk++) {
            uint32_t a[2][4];
            ldsm4(a[0], abm[0] ^ ((uint32_t)(2 * kk) << 4));
            ldsm4(a[1], abm[1] ^ ((uint32_t)(2 * kk) << 4));
            #pragma unroll
            for (int jj = 0; jj < 4; jj++) {
                const int nt = 4 * nw + jj;
                uint4 bf = M1v[(kk * 8 + nt) * 32 + lane];
                #pragma unroll
                for (int mi = 0; mi < 2; mi++) {
                    mma16816h(acc[mi][2 * jj],     a[mi], bf.x, bf.z);
                    mma16816h(acc[mi][2 * jj + 1], a[mi], bf.y, bf.w);
                }
            }
        }
    };

    // scatter B acc -> T1 in buf (row = 16*o1+o2, chunk=i0, XOR ^(o2&7))
    auto scatterB = [&](uint32_t bufo, uint32_t (&acc)[2][8][2]) {
        const int o2v = 8 * (msel & 1) + mrow;
        const int li0 = 2 * mw + (msel >> 1);
        const uint32_t swz = (uint32_t)(li0 ^ mrow) << 4;
        #pragma unroll
        for (int slot = 0; slot < 8; slot++) {
            const int o1 = 8 * nw + slot;
            stsm4(abase + bufo + (uint32_t)(16 * o1 + o2v) * 256 + swz,
                  acc[0][slot][0], acc[0][slot][1],
                  acc[1][slot][0], acc[1][slot][1]);
        }
    };

    // C: T1 (256x128) @ M0^T; 16 warps x 16 rows; f16 acc 4 regs
    auto stageC = [&](uint32_t bufo, uint32_t (&acc)[2][2]) {
        acc[0][0] = acc[0][1] = acc[1][0] = acc[1][1] = 0u;
        const int row = 16 * w + lsel;
        const uint32_t base = abase + bufo + (uint32_t)row * 256;
        #pragma unroll
        for (int ks = 0; ks < 8; ks++) {
            uint32_t a[4];
            ldsm4(a, base + ((uint32_t)((2 * ks + hi) ^ (lsel & 7)) << 4));
            uint4 bf = M0v[ks * 32 + lane];
            mma16816h(acc[0], a, bf.x, bf.z);
            mma16816h(acc[1], a, bf.y, bf.w);
        }
    };

    // epilogue transpose: stmatrix.x4.trans -> Yh[o0][272] halves
    auto epiT = [&](uint32_t yho, uint32_t (&acc)[2][2]) {
        const uint32_t addr = abase + yho +
            ((uint32_t)(mrow + 8 * (msel >> 1)) * 272 +
             (uint32_t)(16 * w + 8 * (msel & 1))) * 2;
        stsm4t(addr, acc[0][0], acc[0][1], acc[1][0], acc[1][1]);
    };

    auto epiOut = [&](uint32_t yho, float* yr) {
        const int o0 = tid >> 5, coll = (tid & 31) * 8;
        uint4 hv = *(const uint4*)(scp + yho + ((uint32_t)o0 * 272 + coll) * 2);
        float2 p0 = __half22float2(*(__half2*)&hv.x);
        float2 p1 = __half22float2(*(__half2*)&hv.y);
        float2 p2 = __half22float2(*(__half2*)&hv.z);
        float2 p3 = __half22float2(*(__half2*)&hv.w);
        const int i = o0 * 256 + coll;
        float4 b0 = *(const float4*)&bias[i];
        float4 b1 = *(const float4*)&bias[i + 4];
        float4 v0 = {p0.x + b0.x, p0.y + b0.y, p1.x + b0.z, p1.y + b0.w};
        float4 v1 = {p2.x + b1.x, p2.y + b1.y, p3.x + b1.z, p3.y + b1.w};
        *(float4*)&yr[i]     = v0;
        *(float4*)&yr[i + 4] = v1;
    };

    // =================== pipelined schedule (5 syncs / 2 rows) ==============
    uint32_t a0[4], a1[4];
    loadpack(xr0, a0);
    stageA(a0, B_BUF0);                       // R1
    __syncthreads();

    loadpack(xr1, a1);                        // R2: x(1) LDG early
    uint32_t accb0[2][8][2];
    stageB(B_BUF0, accb0);                    //     tensor on row0
    stageA(a1, B_BUF1);                       //     memory+mma on row1
    __syncthreads();

    scatterB(B_BUF0, accb0);                  // R3 (accb0 dies here)
    uint32_t accb1[2][8][2];
    stageB(B_BUF1, accb1);                    //     tensor on row1
    __syncthreads();

    uint32_t accc0[2][2];
    stageC(B_BUF0, accc0);                    // R4
    scatterB(B_BUF1, accb1);
    __syncthreads();

    epiT(B_YH0, accc0);                       // R5
    uint32_t accc1[2][2];
    stageC(B_BUF1, accc1);
    epiT(B_YH1, accc1);
    __syncthreads();

    epiOut(B_YH0, y + (size_t)(2 * b2) * 4096);     // R6
    epiOut(B_YH1, y + (size_t)(2 * b2 + 1) * 4096);
}

extern "C" void kernel_launch(void* const* d_in, const int* in_sizes, int n_in,
                              void* d_out, int out_size) {
    const float* x    = (const float*)d_in[0];
    const float* c0   = (const float*)d_in[1];
    const float* c1   = (const float*)d_in[2];
    const float* c2   = (const float*)d_in[3];
    const float* bias = (const float*)d_in[4];
    float* y = (float*)d_out;

    cudaFuncSetAttribute(tt_linear_kernel,
                         cudaFuncAttributeMaxDynamicSharedMemorySize,
                         SMEM_BYTES);

    tt_prep_cores<<<4, 512>>>(c0, c1, c2);
    tt_linear_kernel<<<4096, 512, SMEM_BYTES>>>(x, bias, y);
}

// round 14
// speedup vs baseline: 1.1652x; 1.1652x over previous
#include <cuda_runtime.h>
#include <cuda_fp16.h>
#include <stdint.h>

// ---------------------------------------------------------------------------
// TT-linear fused kernel, v14 = v13 with stage-A store reverted to v11's
// stsm4 (stmatrix data regs are warp-uniform positional; per-lane register
// selection in R13 was invalid). Persistent 4-row CTAs + cp.async
// double-buffered x prefetch. 2 CTAs/SM, 8 warps, aliased 64KB buffer.
// ---------------------------------------------------------------------------

#define B_XS0  65536
#define B_XS1  81920
#define SMEM_BYTES (98304 + 1024)
#define ROWS_PER_CTA 4

// fragment-ordered core matrices (fp16), layouts as v10/v11 (passing):
__device__ __half g_M1f[8 * 8 * 32 * 8];   // 32KB
__device__ __half g_M2f[16 * 32 * 4];      // 4KB
__device__ __half g_M0f[8 * 32 * 8];       // 4KB

__global__ void tt_prep_cores(const float* __restrict__ c0,
                              const float* __restrict__ c1,
                              const float* __restrict__ c2) {
    int t = blockIdx.x * blockDim.x + threadIdx.x;
    int lane = t & 31, g = (lane >> 2), c = lane & 3;
    if (t < 2048) {                       // M1f: (kk, nt, lane)
        int kk = t >> 8, nt = (t >> 5) & 7;
        #pragma unroll
        for (int r = 0; r < 4; r++)
            #pragma unroll
            for (int h = 0; h < 2; h++) {
                int n = 16 * nt + g + 8 * (r & 1);
                int k = 16 * kk + 8 * (r >> 1) + 2 * c + h;
                int o1 = n >> 3, r1 = n & 7, i1 = k >> 3, r2 = k & 7;
                g_M1f[t * 8 + r * 2 + h] =
                    __float2half(c1[((r1 * 16 + o1) * 16 + i1) * 8 + r2]);
            }
    }
    if (t < 512) {                        // M2f: (nt8, lane)
        int nt8 = t >> 5;
        #pragma unroll
        for (int r = 0; r < 2; r++)
            #pragma unroll
            for (int h = 0; h < 2; h++) {
                int n = 8 * nt8 + g;
                int k = 8 * r + 2 * c + h;            // logical mma-k
                int o2 = n >> 3, r2 = n & 7;
                int cc = (k >> 1) & 3, d = k & 1, e = k >> 3;
                int i2 = 4 * cc + 2 * e + d;          // sigma(k)
                g_M2f[t * 4 + r * 2 + h] =
                    __float2half(c2[(r2 * 16 + o2) * 16 + i2]);
            }
    }
    if (t < 256) {                        // M0f: (ks=0..7, lane)
        int ks = t >> 5;
        #pragma unroll
        for (int r = 0; r < 4; r++)
            #pragma unroll
            for (int h = 0; h < 2; h++) {
                int n = g + 8 * (r & 1);              // o0
                int k = 16 * ks + 8 * (r >> 1) + 2 * c + h;
                int i0 = k >> 3, r1 = k & 7;
                g_M0f[t * 8 + r * 2 + h] =
                    __float2half(c0[(n * 16 + i0) * 8 + r1]);
            }
    }
}

__device__ __forceinline__ void mma16816h(uint32_t* d, const uint32_t* a,
                                          uint32_t b0, uint32_t b1) {
    asm volatile(
        "mma.sync.aligned.m16n8k16.row.col.f16.f16.f16.f16 "
        "{%0,%1}, {%2,%3,%4,%5}, {%6,%7}, {%0,%1};\n"
        : "+r"(d[0]), "+r"(d[1])
        : "r"(a[0]), "r"(a[1]), "r"(a[2]), "r"(a[3]), "r"(b0), "r"(b1));
}

__device__ __forceinline__ void ldsm4(uint32_t* r, uint32_t addr) {
    asm volatile(
        "ldmatrix.sync.aligned.m8n8.x4.shared.b16 {%0,%1,%2,%3}, [%4];\n"
        : "=r"(r[0]), "=r"(r[1]), "=r"(r[2]), "=r"(r[3]) : "r"(addr));
}

__device__ __forceinline__ void stsm4(uint32_t addr, uint32_t r0, uint32_t r1,
                                      uint32_t r2, uint32_t r3) {
    asm volatile(
        "stmatrix.sync.aligned.m8n8.x4.shared.b16 [%0], {%1,%2,%3,%4};\n"
        :: "r"(addr), "r"(r0), "r"(r1), "r"(r2), "r"(r3) : "memory");
}

__device__ __forceinline__ void cpa16(uint32_t saddr, const void* gaddr) {
    asm volatile("cp.async.cg.shared.global [%0], [%1], 16;\n"
                 :: "r"(saddr), "l"(gaddr));
}
__device__ __forceinline__ void cpa_commit() {
    asm volatile("cp.async.commit_group;\n" ::: "memory");
}
__device__ __forceinline__ void cpa_wait0() {
    asm volatile("cp.async.wait_group 0;\n" ::: "memory");
}

__device__ __forceinline__ uint32_t packh2(float lo, float hi) {
    __half2 h = __floats2half2_rn(lo, hi);
    return *(uint32_t*)&h;
}

__global__ void __launch_bounds__(256, 2)
tt_linear_kernel(const float* __restrict__ x, const float* __restrict__ bias,
                 float* __restrict__ y) {
    extern __shared__ __half smem[];
    uint32_t sbase;
    asm("{ .reg .u64 t; cvta.to.shared.u64 t, %1; cvt.u32.u64 %0, t; }"
        : "=r"(sbase) : "l"(smem));
    const uint32_t abase = (sbase + 1023) & ~1023u;
    char* scp = (char*)smem + (abase - sbase);
    float* Ysm = (float*)scp;             // aliases BUF at epilogue

    const int tid  = threadIdx.x;
    const int w    = tid >> 5;
    const int lane = tid & 31;
    const int g = lane >> 2, c = lane & 3;
    const int lsel = lane & 15;
    const int hi   = lane >> 4;
    const int msel = lane >> 3;            // stmatrix matrix id
    const int mrow = lane & 7;             // stmatrix row-in-matrix

    const int mw = w & 3;                  // stage B m-warp
    const int nw = w >> 2;                 // stage B n-warp

    const float* xr0 = x + (size_t)blockIdx.x * ROWS_PER_CTA * 4096;
    float*       yr0 = y + (size_t)blockIdx.x * ROWS_PER_CTA * 4096;
    const uint4* M1v = (const uint4*)g_M1f;
    const uint2* M2v = (const uint2*)g_M2f;
    const uint4* M0v = (const uint4*)g_M0f;

    // thread-private x staging offsets (bytes within a 16KB row image):
    // this thread reads floats at (2w+mi)*256 + 16g + 4c (+128), mi=0,1
    const uint32_t xo = ((uint32_t)(2 * w) * 256 + 16 * g + 4 * c) * 4;

    auto prefetchX = [&](const float* xr, uint32_t xsb) {
        cpa16(abase + xsb + xo,        (const char*)xr + xo);
        cpa16(abase + xsb + xo + 512,  (const char*)xr + xo + 512);
        cpa16(abase + xsb + xo + 1024, (const char*)xr + xo + 1024);
        cpa16(abase + xsb + xo + 1536, (const char*)xr + xo + 1536);
        cpa_commit();
    };

    // ---- prologue: prefetch row 0 ----
    prefetchX(xr0, B_XS0);

    #pragma unroll 1
    for (int r = 0; r < ROWS_PER_CTA; r++) {
        const uint32_t xsb = (r & 1) ? B_XS1 : B_XS0;
        float* yr = yr0 + (size_t)r * 4096;

        // =================================================================
        // stage A: x (256x16 logical) @ M2^T -> BUF as T2.
        // warp w owns i0 in {2w, 2w+1}; x read from smem staging.
        // T2: row = i0*16 + o2 (256 rows x 256B), chunk = i1, XOR ^(row&7).
        // stsm4: addr groups carry li0 = 2w+(msel>>1), i1 = mrow+8(msel&1);
        // data regs are warp-uniform positional {d0lo, d0hi, d1lo, d1hi}.
        // =================================================================
        cpa_wait0();   // row-r staging complete (thread-private chunks)
        {
            uint32_t a[2][4];
            #pragma unroll
            for (int mi = 0; mi < 2; mi++) {
                const char* rp = scp + xsb + xo + (uint32_t)mi * 1024;
                float4 f0 = *(const float4*)(rp);
                float4 f1 = *(const float4*)(rp + 512);
                a[mi][0] = packh2(f0.x, f0.y);
                a[mi][1] = packh2(f1.x, f1.y);
                a[mi][2] = packh2(f0.z, f0.w);
                a[mi][3] = packh2(f1.z, f1.w);
            }
            const int i1s = mrow + 8 * (msel & 1);    // stsm source row
            const int li0s = 2 * w + (msel >> 1);
            #pragma unroll
            for (int nt8 = 0; nt8 < 16; nt8++) {      // o2
                uint2 bf = M2v[nt8 * 32 + lane];
                uint32_t d[2][2];
                #pragma unroll
                for (int mi = 0; mi < 2; mi++) {
                    d[mi][0] = 0u; d[mi][1] = 0u;
                    mma16816h(d[mi], a[mi], bf.x, bf.y);
                }
                const uint32_t swo = ((uint32_t)(i1s ^ (nt8 & 7))) << 4;
                stsm4(abase + (uint32_t)(16 * li0s + nt8) * 256 + swo,
                      d[0][0], d[0][1], d[1][0], d[1][1]);
            }
        }
        // prefetch next row's x during the tensor-heavy phase
        if (r + 1 < ROWS_PER_CTA)
            prefetchX(xr0 + (size_t)(r + 1) * 4096,
                      ((r + 1) & 1) ? B_XS1 : B_XS0);
        __syncthreads();

        // =================================================================
        // stage B: T2 (256x128) @ M1^T, single pass, f16 acc (64 regs).
        // warp grid 4M x 2N: per warp 4 mi (64 m-rows), 4 jj (64 n-cols).
        // =================================================================
        uint32_t accb[4][8][2];
        #pragma unroll
        for (int mi = 0; mi < 4; mi++)
            #pragma unroll
            for (int s = 0; s < 8; s++) {
                accb[mi][s][0] = 0u; accb[mi][s][1] = 0u;
            }
        {
            uint32_t abm[4];
            #pragma unroll
            for (int mi = 0; mi < 4; mi++) {
                const int ar = 64 * mw + 16 * mi + lsel;
                abm[mi] = abase + (uint32_t)ar * 256 +
                          ((uint32_t)(hi ^ (ar & 7)) << 4);
            }
            #pragma unroll
            for (int kk = 0; kk < 8; kk++) {
                uint32_t a[4][4];
                #pragma unroll
                for (int mi = 0; mi < 4; mi++)
                    ldsm4(a[mi], abm[mi] ^ ((uint32_t)(2 * kk) << 4));
                #pragma unroll
                for (int jj = 0; jj < 4; jj++) {
                    const int nt = 4 * nw + jj;       // 16-wide n-tile
                    uint4 bf = M1v[(kk * 8 + nt) * 32 + lane];
                    #pragma unroll
                    for (int mi = 0; mi < 4; mi++) {
                        mma16816h(accb[mi][2 * jj],     a[mi], bf.x, bf.z);
                        mma16816h(accb[mi][2 * jj + 1], a[mi], bf.y, bf.w);
                    }
                }
            }
        }
        __syncthreads();   // all T2 reads done; BUF reusable as T1

        // scatter to T1 (aliased): row = 16*o1 + o2, chunk = i0, XOR ^(o2&7)
        {
            const int o2v = mrow + 8 * (msel & 1);
            #pragma unroll
            for (int p = 0; p < 2; p++) {
                const int c16 = 4 * mw + 2 * p + (msel >> 1);   // i0
                const uint32_t swo = ((uint32_t)(c16 ^ mrow)) << 4;
                #pragma unroll
                for (int slot = 0; slot < 8; slot++) {
                    const int o1 = 8 * nw + slot;
                    stsm4(abase + (uint32_t)(16 * o1 + o2v) * 256 + swo,
                          accb[2 * p][slot][0],     accb[2 * p][slot][1],
                          accb[2 * p + 1][slot][0], accb[2 * p + 1][slot][1]);
                }
            }
        }
        __syncthreads();

        // =================================================================
        // stage C: T1 (256x128) @ M0^T -> f16 accumulators (8 regs)
        // =================================================================
        uint32_t accc[2][2][2];
        #pragma unroll
        for (int mi = 0; mi < 2; mi++)
            #pragma unroll
            for (int nt = 0; nt < 2; nt++) {
                accc[mi][nt][0] = 0u; accc[mi][nt][1] = 0u;
            }
        #pragma unroll
        for (int ks = 0; ks < 8; ks++) {
            uint32_t a[2][4];
            #pragma unroll
            for (int mi = 0; mi < 2; mi++) {
                const int row = 16 * (w + 8 * mi) + lsel;
                ldsm4(a[mi], abase + (uint32_t)row * 256 +
                             ((uint32_t)((2 * ks + hi) ^ (lsel & 7)) << 4));
            }
            uint4 bf = M0v[ks * 32 + lane];
            #pragma unroll
            for (int mi = 0; mi < 2; mi++) {
                mma16816h(accc[mi][0], a[mi], bf.x, bf.z);
                mma16816h(accc[mi][1], a[mi], bf.y, bf.w);
            }
        }
        __syncthreads();   // T1 reads done; BUF reusable as Ysm

        // ---- epilogue: transpose through Ysm (stride 260), float4 out ----
        #pragma unroll
        for (int mi = 0; mi < 2; mi++) {
            const int row0 = 16 * (w + 8 * mi) + g;   // o1*16+o2
            #pragma unroll
            for (int nt = 0; nt < 2; nt++) {
                const int col0 = 8 * nt + 2 * c;      // o0
                float2 v0 = __half22float2(*(__half2*)&accc[mi][nt][0]);
                float2 v1 = __half22float2(*(__half2*)&accc[mi][nt][1]);
                Ysm[(col0)     * 260 + row0]     = v0.x;
                Ysm[(col0 + 1) * 260 + row0]     = v0.y;
                Ysm[(col0)     * 260 + row0 + 8] = v1.x;
                Ysm[(col0 + 1) * 260 + row0 + 8] = v1.y;
            }
        }
        __syncthreads();

        #pragma unroll
        for (int it = 0; it < 4; it++) {
            const int i = 4 * (tid + 256 * it);       // i = o0*256 + row
            const int o0 = i >> 8, row = i & 255;
            float4 v = *(const float4*)&Ysm[o0 * 260 + row];
            float4 bb = *(const float4*)&bias[i];
            v.x += bb.x; v.y += bb.y; v.z += bb.z; v.w += bb.w;
            *(float4*)&yr[i] = v;
        }
        __syncthreads();   // Ysm reads done before next row's stage A
    }
}

extern "C" void kernel_launch(void* const* d_in, const int* in_sizes, int n_in,
                              void* d_out, int out_size) {
    const float* x    = (const float*)d_in[0];
    const float* c0   = (const float*)d_in[1];
    const float* c1   = (const float*)d_in[2];
    const float* c2   = (const float*)d_in[3];
    const float* bias = (const float*)d_in[4];
    float* y = (float*)d_out;

    cudaFuncSetAttribute(tt_linear_kernel,
                         cudaFuncAttributeMaxDynamicSharedMemorySize,
                         SMEM_BYTES);

    tt_prep_cores<<<4, 512>>>(c0, c1, c2);
    tt_linear_kernel<<<8192 / ROWS_PER_CTA, 256, SMEM_BYTES>>>(x, bias, y);
}